// round 12
// baseline (speedup 1.0000x reference)
#include <cuda_runtime.h>
#include <cuda_bf16.h>

#define BATCH    8
#define NVERTS   468
#define NTRI     256
#define IMG      1024
#define TILE_W   32
#define TILE_H   32
#define TILES_X  (IMG / TILE_W)    // 32
#define TILES_Y  (IMG / TILE_H)    // 32
#define FULL_EPS 1e-5f
#define BIG_AREA2 0.2f

#define LM_FLOATS   (NVERTS * 3)   // 1404 floats (5616 B)
#define TRI_INTS    (NTRI * 3)     // 768 ints   (3072 B)
#define STRIDE      (NTRI + 2)     // SoA row stride (room for odd-pad slot)

typedef unsigned long long ull;

__device__ __forceinline__ ull pk2(float lo, float hi) {
    ull r;
    asm("mov.b64 %0, {%1, %2};" : "=l"(r) : "f"(lo), "f"(hi));
    return r;
}
__device__ __forceinline__ ull fma2(ull a, ull b, ull c) {
    ull d;
    asm("fma.rn.f32x2 %0, %1, %2, %3;" : "=l"(d) : "l"(a), "l"(b), "l"(c));
    return d;
}

// --------------------------------------------------------------- fused ----
// One block per 32x32 tile (8192 blocks).
// Phase 0: stage landmarks+tri coalesced into smem (overlaid on SoA arrays).
// Phase 1: thread t computes triangle t's edge coefs/bbox; tile full-cover
//          vote; ballot-compact into 9 SoA arrays (big-area bucket first);
//          odd count padded by duplicating the last slot (idempotent).
// Phase 2: warp w owns rows [4w,4w+4). Triangles processed in PAIRS: slots
//          (k,k+1) of each SoA array load as one LDS.64 feeding fma.f32x2
//          (lo=tri k, hi=tri k+1). Sign logic as 64-bit bitops (paired
//          LOP3, no movs). Band-local warp vote every pair.
__global__ __launch_bounds__(256)
void fused_kernel(const float* __restrict__ lm,
                  const int* __restrict__ tri,
                  float* __restrict__ out) {
    __shared__ __align__(16) float s_soa[9 * STRIDE];   // 9288 B
    __shared__ int s_offA[8], s_offB[8];
    __shared__ int s_cnt;

    float* s_lmf  = s_soa;                                   // staging overlay
    int*   s_trii = reinterpret_cast<int*>(s_soa + LM_FLOATS);

    float* sA0 = s_soa + 0 * STRIDE;  float* sB0 = s_soa + 1 * STRIDE;
    float* sC0 = s_soa + 2 * STRIDE;  float* sA1 = s_soa + 3 * STRIDE;
    float* sB1 = s_soa + 4 * STRIDE;  float* sC1 = s_soa + 5 * STRIDE;
    float* sA2 = s_soa + 6 * STRIDE;  float* sB2 = s_soa + 7 * STRIDE;
    float* sC2 = s_soa + 8 * STRIDE;

    const int b   = blockIdx.z;
    const int t   = threadIdx.x;
    const int wid = t >> 5, lid = t & 31;

    // ---- Phase 0: coalesced staging ----
    {
        const float4* src = reinterpret_cast<const float4*>(lm + (size_t)b * LM_FLOATS);
        float4* dst = reinterpret_cast<float4*>(s_soa);
        for (int i = t; i < LM_FLOATS / 4; i += 256) dst[i] = src[i];
        const int4* tsrc = reinterpret_cast<const int4*>(tri);
        int4* tdst = reinterpret_cast<int4*>(s_soa + LM_FLOATS);
        for (int i = t; i < TRI_INTS / 4; i += 256) tdst[i] = tsrc[i];
    }
    __syncthreads();

    // ---- Phase 1: per-triangle setup from smem ----
    const int i0 = s_trii[t * 3 + 0];
    const int i1 = s_trii[t * 3 + 1];
    const int i2 = s_trii[t * 3 + 2];
    const float ax = s_lmf[i0 * 3 + 0], ay = s_lmf[i0 * 3 + 1];
    const float bx = s_lmf[i1 * 3 + 0], by = s_lmf[i1 * 3 + 1];
    const float cx = s_lmf[i2 * 3 + 0], cy = s_lmf[i2 * 3 + 1];

    // edge(P,Q)(px,py) = -(Qy-Py)*px + (Qx-Px)*py + [(Qy-Py)*Px - (Qx-Px)*Py]
    float4 e0, e1, e2;
    { float dX = cx - bx, dY = cy - by;
      e0 = make_float4(-dY, dX, fmaf(dY, bx, -(dX * by)), 0.0f); }
    { float dX = ax - cx, dY = ay - cy;
      e1 = make_float4(-dY, dX, fmaf(dY, cx, -(dX * cy)), 0.0f); }
    { float dX = bx - ax, dY = by - ay;
      e2 = make_float4(-dY, dX, fmaf(dY, ax, -(dX * ay)), 0.0f); }

    // Tile extreme pixel centers: p = 1 - (idx + 0.5)/IMG
    const float pxmin = 1.0f - ((float)(blockIdx.x * TILE_W) + (TILE_W - 0.5f)) * (1.0f / IMG);
    const float pxmax = 1.0f - ((float)(blockIdx.x * TILE_W) + 0.5f)            * (1.0f / IMG);
    const float pymin = 1.0f - ((float)(blockIdx.y * TILE_H) + (TILE_H - 0.5f)) * (1.0f / IMG);
    const float pymax = 1.0f - ((float)(blockIdx.y * TILE_H) + 0.5f)            * (1.0f / IMG);

    const bool hit =
        (fminf(ax, fminf(bx, cx)) <= pxmax) && (fmaxf(ax, fmaxf(bx, cx)) >= pxmin) &&
        (fminf(ay, fminf(by, cy)) <= pymax) && (fmaxf(ay, fmaxf(by, cy)) >= pymin);

    bool full = false;
    if (hit) {
        float mn =  1e30f, mx = -1e30f;
        #pragma unroll
        for (int c = 0; c < 4; ++c) {
            const float cx_ = (c & 1) ? pxmax : pxmin;
            const float cy_ = (c & 2) ? pymax : pymin;
            const float w0 = fmaf(e0.x, cx_, fmaf(e0.y, cy_, e0.z));
            const float w1 = fmaf(e1.x, cx_, fmaf(e1.y, cy_, e1.z));
            const float w2 = fmaf(e2.x, cx_, fmaf(e2.y, cy_, e2.z));
            mn = fminf(mn, fminf(w0, fminf(w1, w2)));
            mx = fmaxf(mx, fmaxf(w0, fmaxf(w1, w2)));
        }
        full = (mn >= FULL_EPS) || (mx <= -FULL_EPS);
    }

    // Warp w owns rows [4w, 4w+4); lane = column.
    const int x  = blockIdx.x * TILE_W + lid;
    const int y0 = blockIdx.y * TILE_H + wid * 4;
    const size_t obase = ((size_t)b << 20) + (size_t)y0 * IMG + x;

    // Barrier also fences staged-input reads before compaction overwrites.
    if (__syncthreads_or(full ? 1 : 0)) {   // tile fully covered
        out[obase]           = 1.0f;
        out[obase + IMG]     = 1.0f;
        out[obase + 2 * IMG] = 1.0f;
        out[obase + 3 * IMG] = 1.0f;
        return;
    }

    // Two-bucket compaction (big-area first) into SoA arrays.
    const float area2 = fabsf((bx - ax) * (cy - ay) - (by - ay) * (cx - ax));
    const bool hA = hit && (area2 > BIG_AREA2);
    const bool hB = hit && !(area2 > BIG_AREA2);
    const unsigned mA = __ballot_sync(0xffffffffu, hA);
    const unsigned mB = __ballot_sync(0xffffffffu, hB);
    if (lid == 0) { s_offA[wid] = __popc(mA); s_offB[wid] = __popc(mB); }
    __syncthreads();
    if (t == 0) {
        int s = 0;
        #pragma unroll
        for (int i = 0; i < 8; ++i) { int c = s_offA[i]; s_offA[i] = s; s += c; }
        #pragma unroll
        for (int i = 0; i < 8; ++i) { int c = s_offB[i]; s_offB[i] = s; s += c; }
        s_cnt = s;
    }
    __syncthreads();
    const int cnt = s_cnt;                  // valid: written before barrier
    if (hit) {
        const int pos = hA ? (s_offA[wid] + __popc(mA & ((1u << lid) - 1u)))
                           : (s_offB[wid] + __popc(mB & ((1u << lid) - 1u)));
        sA0[pos] = e0.x;  sB0[pos] = e0.y;  sC0[pos] = e0.z;
        sA1[pos] = e1.x;  sB1[pos] = e1.y;  sC1[pos] = e1.z;
        sA2[pos] = e2.x;  sB2[pos] = e2.y;  sC2[pos] = e2.z;
        if ((cnt & 1) && pos == cnt - 1) {  // pad odd count (idempotent dup)
            sA0[cnt] = e0.x;  sB0[cnt] = e0.y;  sC0[cnt] = e0.z;
            sA1[cnt] = e1.x;  sB1[cnt] = e1.y;  sC1[cnt] = e1.z;
            sA2[cnt] = e2.x;  sB2[cnt] = e2.y;  sC2[cnt] = e2.z;
        }
    }
    __syncthreads();
    const int cnt2 = (cnt + 1) & ~1;        // even, all slots valid

    // ---- Phase 2: 4 contiguous rows/thread, triangle-paired FFMA2 ----
    const float px = 1.0f - ((float)x + 0.5f) * (1.0f / IMG);
    const ull px2 = pk2(px, px);
    const float pyr0 = 1.0f - ((float)(y0 + 0) + 0.5f) * (1.0f / IMG);
    const float pyr1 = 1.0f - ((float)(y0 + 1) + 0.5f) * (1.0f / IMG);
    const float pyr2 = 1.0f - ((float)(y0 + 2) + 0.5f) * (1.0f / IMG);
    const float pyr3 = 1.0f - ((float)(y0 + 3) + 0.5f) * (1.0f / IMG);
    const ull pp0 = pk2(pyr0, pyr0), pp1 = pk2(pyr1, pyr1);
    const ull pp2 = pk2(pyr2, pyr2), pp3 = pk2(pyr3, pyr3);

    // Per row r: 64-bit mask, lo half = tri k, hi half = tri k+1.
    // Not-covered accumulators start all-ones; covered(pixel) <=> lo&hi >= 0.
    ull n0 = ~0ull, n1 = ~0ull, n2 = ~0ull, n3 = ~0ull;

    #pragma unroll 1
    for (int k = 0; k < cnt2; k += 2) {
        const ull A0 = *reinterpret_cast<const ull*>(sA0 + k);
        const ull B0 = *reinterpret_cast<const ull*>(sB0 + k);
        const ull C0 = *reinterpret_cast<const ull*>(sC0 + k);
        const ull A1 = *reinterpret_cast<const ull*>(sA1 + k);
        const ull B1 = *reinterpret_cast<const ull*>(sB1 + k);
        const ull C1 = *reinterpret_cast<const ull*>(sC1 + k);
        const ull A2 = *reinterpret_cast<const ull*>(sA2 + k);
        const ull B2 = *reinterpret_cast<const ull*>(sB2 + k);
        const ull C2 = *reinterpret_cast<const ull*>(sC2 + k);

        const ull u0 = fma2(A0, px2, C0);
        const ull u1 = fma2(A1, px2, C1);
        const ull u2 = fma2(A2, px2, C2);

        {   const ull w0 = fma2(B0, pp0, u0);
            const ull w1 = fma2(B1, pp0, u1);
            const ull w2 = fma2(B2, pp0, u2);
            n0 &= (w0 | w1 | w2) & ~(w0 & w1 & w2); }
        {   const ull w0 = fma2(B0, pp1, u0);
            const ull w1 = fma2(B1, pp1, u1);
            const ull w2 = fma2(B2, pp1, u2);
            n1 &= (w0 | w1 | w2) & ~(w0 & w1 & w2); }
        {   const ull w0 = fma2(B0, pp2, u0);
            const ull w1 = fma2(B1, pp2, u1);
            const ull w2 = fma2(B2, pp2, u2);
            n2 &= (w0 | w1 | w2) & ~(w0 & w1 & w2); }
        {   const ull w0 = fma2(B0, pp3, u0);
            const ull w1 = fma2(B1, pp3, u1);
            const ull w2 = fma2(B2, pp3, u2);
            n3 &= (w0 | w1 | w2) & ~(w0 & w1 & w2); }

        // Row covered <=> (lo & hi) sign clear for that row.
        const int r0 = ((int)(n0 >> 32)) & (int)n0;
        const int r1 = ((int)(n1 >> 32)) & (int)n1;
        const int r2 = ((int)(n2 >> 32)) & (int)n2;
        const int r3 = ((int)(n3 >> 32)) & (int)n3;
        if (__all_sync(0xffffffffu, (r0 | r1 | r2 | r3) >= 0)) break;
    }

    out[obase]           = ((((int)(n0 >> 32)) & (int)n0) >= 0) ? 1.0f : 0.0f;
    out[obase + IMG]     = ((((int)(n1 >> 32)) & (int)n1) >= 0) ? 1.0f : 0.0f;
    out[obase + 2 * IMG] = ((((int)(n2 >> 32)) & (int)n2) >= 0) ? 1.0f : 0.0f;
    out[obase + 3 * IMG] = ((((int)(n3 >> 32)) & (int)n3) >= 0) ? 1.0f : 0.0f;
}

// -------------------------------------------------------------- launch ----
extern "C" void kernel_launch(void* const* d_in, const int* in_sizes, int n_in,
                              void* d_out, int out_size) {
    const float* landmarks = (const float*)d_in[0];   // [8, 468, 3] f32
    const int*   tri       = (const int*)d_in[1];     // [256, 3] i32
    float* out = (float*)d_out;                       // [8, 1024, 1024] f32

    dim3 grid(TILES_X, TILES_Y, BATCH);               // 32 x 32 x 8 = 8192
    fused_kernel<<<grid, 256>>>(landmarks, tri, out);
}

// round 13
// speedup vs baseline: 1.0010x; 1.0010x over previous
#include <cuda_runtime.h>
#include <cuda_bf16.h>

#define BATCH    8
#define NVERTS   468
#define NTRI     256
#define IMG      1024
#define TILE_W   32
#define TILE_H   32
#define TILES_X  (IMG / TILE_W)    // 32
#define TILES_Y  (IMG / TILE_H)    // 32
#define FULL_EPS 1e-5f
#define BIG_AREA2 0.2f

#define LM_FLOATS   (NVERTS * 3)   // 1404 floats (5616 B)
#define TRI_INTS    (NTRI * 3)     // 768 ints   (3072 B)
#define NPAIR       (NTRI / 2 + 1) // 129 pair slots (incl. odd pad)

typedef unsigned long long ull;

__device__ __forceinline__ ull pk2(float lo, float hi) {
    ull r;
    asm("mov.b64 %0, {%1, %2};" : "=l"(r) : "f"(lo), "f"(hi));
    return r;
}
__device__ __forceinline__ ull fma2(ull a, ull b, ull c) {
    ull d;
    asm("fma.rn.f32x2 %0, %1, %2, %3;" : "=l"(d) : "l"(a), "l"(b), "l"(c));
    return d;
}

// Shared layout (bytes): P0,P1,P2,P3 : NPAIR x ulonglong2 (2064 each)
//                        P4          : NPAIR x ull        (1032)
// Total 9288 B; staging overlay (lm 5616 + tri 3072 = 8688 B) fits inside.
#define P_BYTES      (NPAIR * 16)
#define SMEM_BYTES   (4 * P_BYTES + NPAIR * 8)

// --------------------------------------------------------------- fused ----
// One block per 32x32 tile (8192 blocks).
// Phase 0: stage landmarks+tri coalesced into smem (overlaid on P arrays).
// Phase 1: thread t computes triangle t's edge coefs/bbox; tile full-cover
//          vote (sign-selected corners, 2 evals/edge); ballot-compact into
//          pair-packed arrays (big-area bucket first); odd cnt padded by
//          duplicating the last slot (idempotent under AND-accumulate).
// Phase 2: warp w owns rows [4w,4w+4). Per triangle PAIR: 4 LDS.128 +
//          1 LDS.64 yield aligned 64-bit operands feeding fma.f32x2 for all
//          3 edges x 4 rows; sign-bit LOP3 accumulate; band vote per pair.
__global__ __launch_bounds__(256)
void fused_kernel(const float* __restrict__ lm,
                  const int* __restrict__ tri,
                  float* __restrict__ out) {
    __shared__ __align__(16) char s_raw[SMEM_BYTES];
    __shared__ int s_offA[8], s_offB[8];
    __shared__ int s_cnt;

    ulonglong2* P0 = reinterpret_cast<ulonglong2*>(s_raw);
    ulonglong2* P1 = reinterpret_cast<ulonglong2*>(s_raw + P_BYTES);
    ulonglong2* P2 = reinterpret_cast<ulonglong2*>(s_raw + 2 * P_BYTES);
    ulonglong2* P3 = reinterpret_cast<ulonglong2*>(s_raw + 3 * P_BYTES);
    ull*        P4 = reinterpret_cast<ull*>(s_raw + 4 * P_BYTES);
    float* P0f = reinterpret_cast<float*>(P0);
    float* P1f = reinterpret_cast<float*>(P1);
    float* P2f = reinterpret_cast<float*>(P2);
    float* P3f = reinterpret_cast<float*>(P3);
    float* P4f = reinterpret_cast<float*>(P4);

    float* s_lmf  = reinterpret_cast<float*>(s_raw);
    int*   s_trii = reinterpret_cast<int*>(s_raw + LM_FLOATS * 4);

    const int b   = blockIdx.z;
    const int t   = threadIdx.x;
    const int wid = t >> 5, lid = t & 31;

    // ---- Phase 0: coalesced staging ----
    {
        const float4* src = reinterpret_cast<const float4*>(lm + (size_t)b * LM_FLOATS);
        float4* dst = reinterpret_cast<float4*>(s_raw);
        for (int i = t; i < LM_FLOATS / 4; i += 256) dst[i] = src[i];
        const int4* tsrc = reinterpret_cast<const int4*>(tri);
        int4* tdst = reinterpret_cast<int4*>(s_raw + LM_FLOATS * 4);
        for (int i = t; i < TRI_INTS / 4; i += 256) tdst[i] = tsrc[i];
    }
    __syncthreads();

    // ---- Phase 1: per-triangle setup from smem ----
    const int i0 = s_trii[t * 3 + 0];
    const int i1 = s_trii[t * 3 + 1];
    const int i2 = s_trii[t * 3 + 2];
    const float ax = s_lmf[i0 * 3 + 0], ay = s_lmf[i0 * 3 + 1];
    const float bx = s_lmf[i1 * 3 + 0], by = s_lmf[i1 * 3 + 1];
    const float cx = s_lmf[i2 * 3 + 0], cy = s_lmf[i2 * 3 + 1];

    // edge(P,Q)(px,py) = -(Qy-Py)*px + (Qx-Px)*py + [(Qy-Py)*Px - (Qx-Px)*Py]
    float4 e0, e1, e2;
    { float dX = cx - bx, dY = cy - by;
      e0 = make_float4(-dY, dX, fmaf(dY, bx, -(dX * by)), 0.0f); }
    { float dX = ax - cx, dY = ay - cy;
      e1 = make_float4(-dY, dX, fmaf(dY, cx, -(dX * cy)), 0.0f); }
    { float dX = bx - ax, dY = by - ay;
      e2 = make_float4(-dY, dX, fmaf(dY, ax, -(dX * ay)), 0.0f); }

    // Tile extreme pixel centers: p = 1 - (idx + 0.5)/IMG
    const float pxmin = 1.0f - ((float)(blockIdx.x * TILE_W) + (TILE_W - 0.5f)) * (1.0f / IMG);
    const float pxmax = 1.0f - ((float)(blockIdx.x * TILE_W) + 0.5f)            * (1.0f / IMG);
    const float pymin = 1.0f - ((float)(blockIdx.y * TILE_H) + (TILE_H - 0.5f)) * (1.0f / IMG);
    const float pymax = 1.0f - ((float)(blockIdx.y * TILE_H) + 0.5f)            * (1.0f / IMG);

    const bool hit =
        (fminf(ax, fminf(bx, cx)) <= pxmax) && (fmaxf(ax, fmaxf(bx, cx)) >= pxmin) &&
        (fminf(ay, fminf(by, cy)) <= pymax) && (fmaxf(ay, fmaxf(by, cy)) >= pymin);

    // Full-cover via sign-selected extreme corners: affine w attains its
    // min/max over the tile rectangle at corners picked by sign(A), sign(B).
    bool full = false;
    if (hit) {
        float wmn =  1e30f, wmx = -1e30f;
        #pragma unroll
        for (int e = 0; e < 3; ++e) {
            const float4 E = (e == 0) ? e0 : (e == 1) ? e1 : e2;
            const float xlo = (E.x >= 0.0f) ? pxmin : pxmax;
            const float xhi = (E.x >= 0.0f) ? pxmax : pxmin;
            const float ylo = (E.y >= 0.0f) ? pymin : pymax;
            const float yhi = (E.y >= 0.0f) ? pymax : pymin;
            wmn = fminf(wmn, fmaf(E.x, xlo, fmaf(E.y, ylo, E.z)));
            wmx = fmaxf(wmx, fmaf(E.x, xhi, fmaf(E.y, yhi, E.z)));
        }
        full = (wmn >= FULL_EPS) || (wmx <= -FULL_EPS);
    }

    // Warp w owns rows [4w, 4w+4); lane = column.
    const int x  = blockIdx.x * TILE_W + lid;
    const int y0 = blockIdx.y * TILE_H + wid * 4;
    const size_t obase = ((size_t)b << 20) + (size_t)y0 * IMG + x;

    // Barrier also fences staged-input reads before compaction overwrites.
    if (__syncthreads_or(full ? 1 : 0)) {   // tile fully covered
        out[obase]           = 1.0f;
        out[obase + IMG]     = 1.0f;
        out[obase + 2 * IMG] = 1.0f;
        out[obase + 3 * IMG] = 1.0f;
        return;
    }

    // Two-bucket compaction (big-area first) into pair-packed arrays.
    const float area2 = fabsf((bx - ax) * (cy - ay) - (by - ay) * (cx - ax));
    const bool hA = hit && (area2 > BIG_AREA2);
    const bool hB = hit && !(area2 > BIG_AREA2);
    const unsigned mA = __ballot_sync(0xffffffffu, hA);
    const unsigned mB = __ballot_sync(0xffffffffu, hB);
    if (lid == 0) { s_offA[wid] = __popc(mA); s_offB[wid] = __popc(mB); }
    __syncthreads();
    if (t == 0) {
        int s = 0;
        #pragma unroll
        for (int i = 0; i < 8; ++i) { int c = s_offA[i]; s_offA[i] = s; s += c; }
        #pragma unroll
        for (int i = 0; i < 8; ++i) { int c = s_offB[i]; s_offB[i] = s; s += c; }
        s_cnt = s;
    }
    __syncthreads();
    const int cnt = s_cnt;
    if (hit) {
        const int pos = hA ? (s_offA[wid] + __popc(mA & ((1u << lid) - 1u)))
                           : (s_offB[wid] + __popc(mB & ((1u << lid) - 1u)));
        // Pair layout (float view, q = pair*4, h = pos&1):
        //   P0: [q+h]=A0  [q+2+h]=B0     P1: [q+h]=A1  [q+2+h]=B1
        //   P2: [q+h]=A2  [q+2+h]=B2     P3: [q+h]=C0  [q+2+h]=C1
        //   P4: [pair*2+h]=C2
        {
            const int q = (pos >> 1) * 4, h = pos & 1;
            P0f[q + h] = e0.x;  P0f[q + 2 + h] = e0.y;
            P1f[q + h] = e1.x;  P1f[q + 2 + h] = e1.y;
            P2f[q + h] = e2.x;  P2f[q + 2 + h] = e2.y;
            P3f[q + h] = e0.z;  P3f[q + 2 + h] = e1.z;
            P4f[(pos >> 1) * 2 + h] = e2.z;
        }
        if ((cnt & 1) && pos == cnt - 1) {  // pad odd count (idempotent dup)
            const int q = (cnt >> 1) * 4, h = 1;
            P0f[q + h] = e0.x;  P0f[q + 2 + h] = e0.y;
            P1f[q + h] = e1.x;  P1f[q + 2 + h] = e1.y;
            P2f[q + h] = e2.x;  P2f[q + 2 + h] = e2.y;
            P3f[q + h] = e0.z;  P3f[q + 2 + h] = e1.z;
            P4f[(cnt >> 1) * 2 + h] = e2.z;
        }
    }
    __syncthreads();
    const int npair = (cnt + 1) >> 1;

    // ---- Phase 2: 4 contiguous rows/thread, pair-packed FFMA2 ----
    const float px = 1.0f - ((float)x + 0.5f) * (1.0f / IMG);
    const ull px2 = pk2(px, px);
    const float pyr0 = 1.0f - ((float)(y0 + 0) + 0.5f) * (1.0f / IMG);
    const float pyr1 = 1.0f - ((float)(y0 + 1) + 0.5f) * (1.0f / IMG);
    const float pyr2 = 1.0f - ((float)(y0 + 2) + 0.5f) * (1.0f / IMG);
    const float pyr3 = 1.0f - ((float)(y0 + 3) + 0.5f) * (1.0f / IMG);
    const ull pp0 = pk2(pyr0, pyr0), pp1 = pk2(pyr1, pyr1);
    const ull pp2 = pk2(pyr2, pyr2), pp3 = pk2(pyr3, pyr3);

    // Not-covered accumulators (lo half = tri k, hi = tri k+1).
    ull n0 = ~0ull, n1 = ~0ull, n2 = ~0ull, n3 = ~0ull;

    #pragma unroll 1
    for (int p = 0; p < npair; ++p) {
        const ulonglong2 v0 = P0[p];   // A0 pair | B0 pair
        const ulonglong2 v1 = P1[p];   // A1 pair | B1 pair
        const ulonglong2 v2 = P2[p];   // A2 pair | B2 pair
        const ulonglong2 v3 = P3[p];   // C0 pair | C1 pair
        const ull        c2 = P4[p];   // C2 pair

        const ull u0 = fma2(v0.x, px2, v3.x);
        const ull u1 = fma2(v1.x, px2, v3.y);
        const ull u2 = fma2(v2.x, px2, c2);

        {   const ull w0 = fma2(v0.y, pp0, u0);
            const ull w1 = fma2(v1.y, pp0, u1);
            const ull w2 = fma2(v2.y, pp0, u2);
            n0 &= (w0 | w1 | w2) & ~(w0 & w1 & w2); }
        {   const ull w0 = fma2(v0.y, pp1, u0);
            const ull w1 = fma2(v1.y, pp1, u1);
            const ull w2 = fma2(v2.y, pp1, u2);
            n1 &= (w0 | w1 | w2) & ~(w0 & w1 & w2); }
        {   const ull w0 = fma2(v0.y, pp2, u0);
            const ull w1 = fma2(v1.y, pp2, u1);
            const ull w2 = fma2(v2.y, pp2, u2);
            n2 &= (w0 | w1 | w2) & ~(w0 & w1 & w2); }
        {   const ull w0 = fma2(v0.y, pp3, u0);
            const ull w1 = fma2(v1.y, pp3, u1);
            const ull w2 = fma2(v2.y, pp3, u2);
            n3 &= (w0 | w1 | w2) & ~(w0 & w1 & w2); }

        const int r0 = ((int)(n0 >> 32)) & (int)n0;
        const int r1 = ((int)(n1 >> 32)) & (int)n1;
        const int r2 = ((int)(n2 >> 32)) & (int)n2;
        const int r3 = ((int)(n3 >> 32)) & (int)n3;
        if (__all_sync(0xffffffffu, (r0 | r1 | r2 | r3) >= 0)) break;
    }

    out[obase]           = ((((int)(n0 >> 32)) & (int)n0) >= 0) ? 1.0f : 0.0f;
    out[obase + IMG]     = ((((int)(n1 >> 32)) & (int)n1) >= 0) ? 1.0f : 0.0f;
    out[obase + 2 * IMG] = ((((int)(n2 >> 32)) & (int)n2) >= 0) ? 1.0f : 0.0f;
    out[obase + 3 * IMG] = ((((int)(n3 >> 32)) & (int)n3) >= 0) ? 1.0f : 0.0f;
}

// -------------------------------------------------------------- launch ----
extern "C" void kernel_launch(void* const* d_in, const int* in_sizes, int n_in,
                              void* d_out, int out_size) {
    const float* landmarks = (const float*)d_in[0];   // [8, 468, 3] f32
    const int*   tri       = (const int*)d_in[1];     // [256, 3] i32
    float* out = (float*)d_out;                       // [8, 1024, 1024] f32

    dim3 grid(TILES_X, TILES_Y, BATCH);               // 32 x 32 x 8 = 8192
    fused_kernel<<<grid, 256>>>(landmarks, tri, out);
}